// round 12
// baseline (speedup 1.0000x reference)
#include <cuda_runtime.h>
#include <cuda_fp16.h>
#include <cuda_bf16.h>
#include <cstdint>

// Problem constants
#define SIGMA   16
#define P       33
#define Hh      256
#define Wn      256
#define Bn      4
#define Kn      64
#define Nn      (Bn * Kn)          // 256 keypoints per side
#define NPATCH  (2 * Nn * Bn)      // 2048 total patches
#define C1      32
#define O1      31                 // conv1 out spatial (961 positions)
#define C2      64
#define O2      15                 // conv2 out spatial (225 positions)
#define NPOS1   (O1 * O1)          // 961
#define NT1     121                // ceil(961/8)
#define NPOS2   (O2 * O2)          // 225
#define NT2     29                 // ceil(225/8)
#define OUTF    128

// conv1 GEMM: K padded 27 -> 48 (tap-major: k = tap*4 + ic, ic 0..3, ic3 = pad)
#define W1PAD   56                 // halves per w1 row (conflict-free A)
// conv2 GEMM: K = 288 (chunk = ks, within-chunk k permuted so B is contiguous)
#define K2      288
#define KS2     18
#define S2      40                 // h1t halves per position (stride 80B -> 8 mod 32 words)

// smem byte offsets
#define SM_H1T    0                        // 961*40*2 = 76880
#define SM_GAP    76880                    // 64*4
#define SM_SB2    77136                    // 64*4
#define SM_SB1    77392                    // 32*4
#define SM_P2OFF  77520                    // 232*4 = 928
#define SM_PATCH  78448                    // 1089*4*2 = 8712 -> 8720
#define SM_W1H    87168                    // 32*56*2 = 3584
#define SM_P1OFF  90752                    // 968*4 = 3872
#define SMEM_BYTES 94624

__device__ __half g_w1h[C1 * W1PAD];
__device__ uint4  g_w2a[4 * KS2 * 32];     // A fragments: [mtile][ks][lane] -> (a0,a1,a2,a3)
__device__ float  g_feat[(size_t)NPATCH * OUTF];
__device__ float  g_part[256];
__device__ int    g_count;

__device__ __forceinline__ void mma16816(float& c0, float& c1, float& c2, float& c3,
                                         uint32_t a0, uint32_t a1, uint32_t a2, uint32_t a3,
                                         uint32_t b0, uint32_t b1) {
    asm volatile(
        "mma.sync.aligned.m16n8k16.row.col.f32.f16.f16.f32 "
        "{%0,%1,%2,%3}, {%4,%5,%6,%7}, {%8,%9}, {%0,%1,%2,%3};"
        : "+f"(c0), "+f"(c1), "+f"(c2), "+f"(c3)
        : "r"(a0), "r"(a1), "r"(a2), "r"(a3), "r"(b0), "r"(b1));
}

// within-chunk permutation: fragment row r -> logical ic offset (0..15)
__host__ __device__ __forceinline__ int permr(int r) {
    return (r & 1) | (((r >> 3) & 1) << 1) | (((r >> 1) & 3) << 2);
}

// ---------------------------------------------------------------------------
// Prep: w1 (tap-major, fp16, padded) + w2 A-fragments pre-swizzled per lane
// ---------------------------------------------------------------------------
__global__ __launch_bounds__(512) void prep_kernel(
    const float* __restrict__ w1, const float* __restrict__ w2)
{
    int t = blockIdx.x * 512 + threadIdx.x;
    const int N1 = C1 * W1PAD;                 // 1792
    const int N2 = 4 * KS2 * 32 * 4;           // 9216 u32 outputs
    if (t < N1) {
        int oc = t / W1PAD, k = t - oc * W1PAD;
        float v = 0.0f;
        if (k < 36) {
            int tap = k >> 2, ic = k & 3;
            if (ic < 3) v = w1[oc * 27 + ic * 9 + tap];
        }
        g_w1h[t] = __float2half(v);
    } else if (t < N1 + N2) {
        int u = t - N1;                        // ((mt*18+ks)*32+lane)*4 + q
        int q    = u & 3;
        int lane = (u >> 2) & 31;
        int ks   = (u >> 7) % KS2;
        int mt   = (u >> 7) / KS2;
        int g  = lane >> 2;
        int t4 = lane & 3;
        int oc = mt * 16 + g + (q & 1) * 8;
        int kbase = 2 * t4 + (q >> 1) * 8;     // fragment rows kbase, kbase+1
        int tap    = ks >> 1;
        int icbase = (ks & 1) * 16;
        float vlo = w2[oc * K2 + (icbase + permr(kbase)) * 9 + tap];
        float vhi = w2[oc * K2 + (icbase + permr(kbase + 1)) * 9 + tap];
        __half2 h = __floats2half2_rn(vlo, vhi);
        ((uint32_t*)g_w2a)[u] = *(uint32_t*)&h;
    }
}

// ---------------------------------------------------------------------------
// Fused: crop + conv1(HMMA) + conv2(HMMA) + GAP + linear. One block / patch.
// ---------------------------------------------------------------------------
__global__ __launch_bounds__(512, 2) void fused_kernel(
    const float* __restrict__ img_g, const float* __restrict__ img_s,
    const float* __restrict__ kp_g,  const float* __restrict__ kp_s,
    const float* __restrict__ b1,    const float* __restrict__ b2,
    const float* __restrict__ wl,    const float* __restrict__ bl)
{
    extern __shared__ char smraw[];
    __half*   h1t     = (__half*)(smraw + SM_H1T);    // [961][40] channel-last
    float*    gap     = (float*)(smraw + SM_GAP);
    float*    sb2     = (float*)(smraw + SM_SB2);
    float*    sb1     = (float*)(smraw + SM_SB1);
    uint32_t* p2off   = (uint32_t*)(smraw + SM_P2OFF);
    __half*   patch_t = (__half*)(smraw + SM_PATCH);  // [1089][4] channel-last
    __half*   sw1h    = (__half*)(smraw + SM_W1H);
    uint32_t* p1off   = (uint32_t*)(smraw + SM_P1OFF);
    const char* h1b   = smraw + SM_H1T;
    const char* ptb   = smraw + SM_PATCH;

    const int tid  = threadIdx.x;
    const int pidx = blockIdx.x;
    const int side = pidx >> 10;
    const int r    = pidx & 1023;
    const int n    = r >> 2;
    const int b    = r & 3;

    const float* kps = side ? kp_s : kp_g;
    const float* img = side ? img_s : img_g;

    const float kx = kps[n * 2 + 0] * 256.0f;
    const float ky = kps[n * 2 + 1] * 256.0f;
    int sx = (int)floorf(kx) - SIGMA;
    int sy = (int)floorf(ky) - SIGMA;
    sx = min(max(sx, 0), Wn - P);
    sy = min(max(sy, 0), Hh - P);

    // ---- stage: patch (fp16 channel-last), w1, bias, tables ----
    for (int t = tid; t < P * P; t += 512) {
        int y = t / P, x = t - y * P;
        size_t base = (((size_t)b * 3) * Hh + (sy + y)) * Wn + (sx + x);
        float v0 = img[base];
        float v1 = img[base + (size_t)Hh * Wn];
        float v2 = img[base + 2 * (size_t)Hh * Wn];
        __half2* dst = (__half2*)(patch_t + t * 4);
        dst[0] = __floats2half2_rn(v0, v1);
        dst[1] = __floats2half2_rn(v2, 0.0f);
    }
    {
        const uint4* s1 = (const uint4*)g_w1h;
        uint4* d1 = (uint4*)sw1h;
        for (int t = tid; t < (C1 * W1PAD * 2) / 16; t += 512) d1[t] = s1[t];
    }
    if (tid < C1) sb1[tid] = b1[tid];
    if (tid < C2) { sb2[tid] = b2[tid]; gap[tid] = 0.0f; }
    for (int t = tid; t < 968; t += 512) {
        int pp = min(t, NPOS1 - 1);
        p1off[t] = (uint32_t)((pp / O1) * P + (pp % O1));   // patch spatial (33-wide)
    }
    if (tid < 232) {
        int pp = min(tid, NPOS2 - 1);
        p2off[tid] = (uint32_t)((pp / O2) * (2 * O1) + (pp % O2) * 2);  // h1 position idx
    }
    __syncthreads();

    const int wid  = tid >> 5;
    const int lane = tid & 31;
    const int g    = lane >> 2;
    const int t4   = lane & 3;

    // ---- conv1 via HMMA: D[32 x 968] = W1[32 x 48] @ im2col(patch)[48 x 968] ----
    {
        const int mb      = (wid & 1) * 16;
        const int nslice  = wid >> 1;            // 0..7
        const int th      = t4 >> 1;
        const int icsel   = (t4 & 1) * 4;        // byte offset into 4-ch slot

        uint32_t A[3][4];
        const __half* a1b = sw1h + (mb + g) * W1PAD + t4 * 2;
        #pragma unroll
        for (int ks = 0; ks < 3; ks++) {
            A[ks][0] = *(const uint32_t*)(a1b + ks * 16);
            A[ks][1] = *(const uint32_t*)(a1b + ks * 16 + 8 * W1PAD);
            A[ks][2] = *(const uint32_t*)(a1b + ks * 16 + 8);
            A[ks][3] = *(const uint32_t*)(a1b + ks * 16 + 8 * W1PAD + 8);
        }
        uint32_t tsA[3], tsB[3];
        #pragma unroll
        for (int ks = 0; ks < 3; ks++) {
            int ta = ks * 4 + th;
            int tb = ks * 4 + 2 + th;
            tsA[ks] = (ta < 9) ? (uint32_t)((ta / 3) * P + ta % 3) : 0u;
            tsB[ks] = (tb < 9) ? (uint32_t)((tb / 3) * P + tb % 3) : 0u;
        }
        const float bias0 = sb1[mb + g];
        const float bias1 = sb1[mb + 8 + g];

        for (int j = 0; j < 16; j++) {
            int nt = nslice + 8 * j;
            if (nt >= NT1) break;
            uint32_t pb = p1off[nt * 8 + g] * 8u + (uint32_t)icsel;
            float c0 = bias0, c1 = bias0, c2 = bias1, c3 = bias1;
            #pragma unroll
            for (int ks = 0; ks < 3; ks++) {
                uint32_t b0 = *(const uint32_t*)(ptb + pb + tsA[ks] * 8u);
                uint32_t b1v = *(const uint32_t*)(ptb + pb + tsB[ks] * 8u);
                mma16816(c0, c1, c2, c3,
                         A[ks][0], A[ks][1], A[ks][2], A[ks][3], b0, b1v);
            }
            int p0 = nt * 8 + t4 * 2;
            if (p0 < NPOS1) {
                h1t[p0 * S2 + mb + g]     = __float2half(fmaxf(c0, 0.0f));
                h1t[p0 * S2 + mb + 8 + g] = __float2half(fmaxf(c2, 0.0f));
            }
            if (p0 + 1 < NPOS1) {
                h1t[(p0 + 1) * S2 + mb + g]     = __float2half(fmaxf(c1, 0.0f));
                h1t[(p0 + 1) * S2 + mb + 8 + g] = __float2half(fmaxf(c3, 0.0f));
            }
        }
    }
    __syncthreads();

    // ---- conv2 via HMMA: D[64 x 232] = W2[64 x 288] @ im2col(h1t)[288 x 232] ----
    // Two sequential n-passes of 4 tiles each -> live regs fit 62 (no spills).
    {
        const int mtile  = wid & 3;
        const int nslice = wid >> 2;
        const int mbase  = mtile * 16;

        const float bias0 = sb2[mbase + g];
        const float bias1 = sb2[mbase + 8 + g];
        const uint4* aPtr = g_w2a + (size_t)mtile * KS2 * 32 + lane;

        float vA = 0.0f, vB = 0.0f;      // GAP partials across both passes

        #pragma unroll 1
        for (int pass = 0; pass < 2; pass++) {
            float c[4][4];
            uint32_t pbyte[4];
            #pragma unroll
            for (int jj = 0; jj < 4; jj++) {
                int nt = nslice + 4 * (pass * 4 + jj);
                if (nt < NT2) {
                    pbyte[jj] = p2off[nt * 8 + g] * (uint32_t)(S2 * 2) + (uint32_t)(t4 * 8);
                    c[jj][0] = bias0; c[jj][1] = bias0;
                    c[jj][2] = bias1; c[jj][3] = bias1;
                }
            }

            uint4 A = __ldg(aPtr);
            #pragma unroll 2
            for (int ks = 0; ks < KS2; ks++) {
                uint4 An;
                if (ks < KS2 - 1) An = __ldg(aPtr + (ks + 1) * 32);
                const int tap = ks >> 1;
                const uint32_t koff = (uint32_t)(((tap / 3) * O1 + tap % 3) * (S2 * 2)
                                                 + (ks & 1) * 32);
                #pragma unroll
                for (int jj = 0; jj < 4; jj++) {
                    int nt = nslice + 4 * (pass * 4 + jj);
                    if (nt < NT2) {
                        const uint2 v = *(const uint2*)(h1b + pbyte[jj] + koff);
                        mma16816(c[jj][0], c[jj][1], c[jj][2], c[jj][3],
                                 A.x, A.y, A.z, A.w, v.x, v.y);
                    }
                }
                A = An;
            }

            #pragma unroll
            for (int jj = 0; jj < 4; jj++) {
                int nt = nslice + 4 * (pass * 4 + jj);
                if (nt < NT2) {
                    int pos0 = nt * 8 + t4 * 2;
                    float m0 = (pos0     < NPOS2) ? 1.0f : 0.0f;
                    float m1 = (pos0 + 1 < NPOS2) ? 1.0f : 0.0f;
                    vA = fmaf(fmaxf(c[jj][0], 0.0f), m0, vA);
                    vA = fmaf(fmaxf(c[jj][1], 0.0f), m1, vA);
                    vB = fmaf(fmaxf(c[jj][2], 0.0f), m0, vB);
                    vB = fmaf(fmaxf(c[jj][3], 0.0f), m1, vB);
                }
            }
        }

        vA += __shfl_xor_sync(0xFFFFFFFF, vA, 1);
        vA += __shfl_xor_sync(0xFFFFFFFF, vA, 2);
        vB += __shfl_xor_sync(0xFFFFFFFF, vB, 1);
        vB += __shfl_xor_sync(0xFFFFFFFF, vB, 2);
        if (t4 == 0) {
            atomicAdd(&gap[mbase + g],     vA);
            atomicAdd(&gap[mbase + 8 + g], vB);
        }
    }
    __syncthreads();

    // ---- linear 64 -> 128 ----
    const float inv = 1.0f / (float)NPOS2;
    if (tid < OUTF) {
        float f = __ldg(&bl[tid]);
        const float* wrow = wl + tid * C2;
        #pragma unroll
        for (int cc = 0; cc < C2; cc++) f = fmaf(gap[cc] * inv, __ldg(&wrow[cc]), f);
        g_feat[(size_t)pidx * OUTF + tid] = f;
    }
}

// ---------------------------------------------------------------------------
// loss = mean((fg - fs)^2), single kernel: 256 partials + last-block reduce
// ---------------------------------------------------------------------------
__global__ __launch_bounds__(256) void loss_kernel(float* __restrict__ out)
{
    const int TOTAL = Nn * Bn * OUTF;     // 131072
    float s = 0.0f;
    for (int i = blockIdx.x * 256 + threadIdx.x; i < TOTAL; i += 256 * 256) {
        float d = g_feat[i] - g_feat[i + TOTAL];
        s = fmaf(d, d, s);
    }
    __shared__ float red[8];
    __shared__ int   amLast;
    #pragma unroll
    for (int off = 16; off > 0; off >>= 1)
        s += __shfl_down_sync(0xFFFFFFFF, s, off);
    int wid = threadIdx.x >> 5;
    int lid = threadIdx.x & 31;
    if (lid == 0) red[wid] = s;
    __syncthreads();
    if (threadIdx.x == 0) {
        float t = 0.0f;
        #pragma unroll
        for (int w = 0; w < 8; w++) t += red[w];
        g_part[blockIdx.x] = t;
        __threadfence();
        int old = atomicAdd(&g_count, 1);
        amLast = (old == gridDim.x - 1);
    }
    __syncthreads();
    if (amLast) {
        // fixed-order tree reduce over the 256 partials
        float v = g_part[threadIdx.x];
        #pragma unroll
        for (int off = 16; off > 0; off >>= 1)
            v += __shfl_down_sync(0xFFFFFFFF, v, off);
        if (lid == 0) red[wid] = v;
        __syncthreads();
        if (threadIdx.x == 0) {
            float t = 0.0f;
            #pragma unroll
            for (int w = 0; w < 8; w++) t += red[w];
            out[0] = t / (float)TOTAL;
            g_count = 0;                 // reset for graph replay
        }
    }
}

extern "C" void kernel_launch(void* const* d_in, const int* in_sizes, int n_in,
                              void* d_out, int out_size)
{
    const float* img_g = (const float*)d_in[0];
    const float* img_s = (const float*)d_in[1];
    const float* kp_g  = (const float*)d_in[2];
    const float* kp_s  = (const float*)d_in[3];
    const float* w1    = (const float*)d_in[4];
    const float* b1    = (const float*)d_in[5];
    const float* w2    = (const float*)d_in[6];
    const float* b2    = (const float*)d_in[7];
    const float* wl    = (const float*)d_in[8];
    const float* bl    = (const float*)d_in[9];
    float* out = (float*)d_out;

    static bool attr_set = false;
    if (!attr_set) {
        cudaFuncSetAttribute(fused_kernel,
                             cudaFuncAttributeMaxDynamicSharedMemorySize, SMEM_BYTES);
        attr_set = true;
    }

    prep_kernel<<<22, 512>>>(w1, w2);
    fused_kernel<<<NPATCH, 512, SMEM_BYTES>>>(img_g, img_s, kp_g, kp_s,
                                              b1, b2, wl, bl);
    loss_kernel<<<256, 256>>>(out);
}